// round 13
// baseline (speedup 1.0000x reference)
#include <cuda_runtime.h>

// MacUnit: out[b, 2*ic+k] = attention[2*ic+k] * f3(data[b, ic])
// f3 = 3 iterations of x += step(x)/3 (tanh-indexed piecewise-linear trig).
//
// R13: output-driven map (out float4 o <- data float2 o, att reg-resident),
// (value,delta) float2 table on [-4,4], h=1/1024, 64KB smem, 2 CTAs/SM
// (regs capped at 32 via __launch_bounds__(1024,2) -- full RF).
// Branchless clamped lookups + ONE warp-ballot fixup per float2 for the
// |x|>=4 tail (<0.4% of warps) replaces 2 per-lane branch envelopes.
// Streaming hints: __ldcs on data (read-once), __stcs on out (write-once).

#define NUM_POINTS 17
#define TAB_INTERVALS 8192               // h = 1/1024 over [-4,4]
#define TAB_SCALE     1024.0f
#define TAB_H         (1.0f / 1024.0f)
#define TAB_BYTES     (TAB_INTERVALS * 8)   // 65536 B of float2

__device__ float2 g_tab[TAB_INTERVALS];

// Exact f3 for one value (rare path + table build).
__device__ __forceinline__ float f3_exact(float x, float c2l, float b2l,
                                          const float* __restrict__ angles,
                                          const float* __restrict__ velocity)
{
    #pragma unroll
    for (int s = 0; s < 3; s++) {
        float e;
        asm("ex2.approx.f32 %0, %1;" : "=f"(e) : "f"(fmaf(x, c2l, b2l)));
        float r;
        asm("rcp.approx.f32 %0, %1;" : "=f"(r) : "f"(e + 1.0f));
        float u = fmaf(r, -17.0f, 17.5f);   // index + 8, in (0.5, 17.5)
        int   si = (int)u;                  // trunc == floor (u > 0)
        float pos = u - (float)si;
        int bgn = si - 8;
        int end = bgn + 1;                  // end < 17 always
        int bw = bgn < 0 ? bgn + NUM_POINTS : bgn;   // torch negative wrap
        int ew = end < 0 ? end + NUM_POINTS : end;
        float vb = __ldg(&velocity[bw]) * (1.0f / 3.0f);
        float ve = __ldg(&velocity[ew]) * (1.0f / 3.0f);
        float ab = __ldg(&angles[bw]);
        float ae = __ldg(&angles[ew]);
        float velo3 = fmaf(pos, ve - vb, vb);
        float ang   = fmaf(pos, ae - ab, ab);
        float sn, cs;
        __sincosf(ang, &sn, &cs);
        x = fmaf(x, fmaf(velo3, sn, 1.0f), velo3 * cs);
    }
    return x;
}

// ---------------------------------------------------------------------------
// Kernel 1: build (value, delta) pair table.
// ---------------------------------------------------------------------------
__global__ __launch_bounds__(256)
void build_table_kernel(const float* __restrict__ angles,
                        const float* __restrict__ velocity,
                        const float* __restrict__ coeff,
                        const float* __restrict__ bias)
{
    const float c2l = __ldg(coeff) * 2.8853900817779268f;   // 2*log2(e)*c
    const float b2l = __ldg(bias)  * 2.8853900817779268f;
    const int i = blockIdx.x * 256 + threadIdx.x;
    if (i < TAB_INTERVALS) {
        float x0 = fmaf((float)i,       TAB_H, -4.0f);
        float x1 = fmaf((float)(i + 1), TAB_H, -4.0f);
        float v0 = f3_exact(x0, c2l, b2l, angles, velocity);
        float v1 = f3_exact(x1, c2l, b2l, angles, velocity);
        g_tab[i] = make_float2(v0, v1 - v0);
    }
}

// ---------------------------------------------------------------------------
// Kernel 2: persistent map, output-driven. 64KB table, 2 CTAs/SM, 4-way ILP.
// ---------------------------------------------------------------------------
#define MAP_THREADS 1024
#define MAP_BLOCKS  304                   // 2 CTAs resident per SM x 152 SMs
#define TOTAL_O     (32768 * 256)         // 8,388,608 output float4s
#define ILP 4

extern __shared__ float2 s_tab[];

// Branchless clamped table lookup (valid result iff |x| < 4).
__device__ __forceinline__ float tab_lookup_fast(float x)
{
    float t = fmaf(x, TAB_SCALE, 4.0f * TAB_SCALE);        // (x+4)/h
    t = fminf(fmaxf(t, 0.0f), 8191.0f);                    // clamp (safe index)
    int   i  = (int)t;
    float fr = t - (float)i;
    float2 vd = s_tab[i];                                  // one LDS.64
    return fmaf(fr, vd.y, vd.x);
}

__global__ __launch_bounds__(MAP_THREADS, 2)
void macunit_map_kernel(const float2* __restrict__ data,   // [B*256] float2
                        const float4* __restrict__ att,    // [256] float4
                        const float* __restrict__ angles,
                        const float* __restrict__ velocity,
                        const float* __restrict__ coeff,
                        const float* __restrict__ bias,
                        float4* __restrict__ out)          // [B*256] float4
{
    // Stage pair table into shared memory.
    {
        const float2* gt = g_tab;
        for (int i = threadIdx.x; i < TAB_INTERVALS; i += MAP_THREADS)
            s_tab[i] = __ldg(&gt[i]);
    }
    __syncthreads();

    const float c2l = __ldg(coeff) * 2.8853900817779268f;
    const float b2l = __ldg(bias)  * 2.8853900817779268f;

    const int t0 = blockIdx.x * MAP_THREADS + threadIdx.x;
    const int stride = MAP_BLOCKS * MAP_THREADS;            // 311296 (mult of 256)

    // Loop-invariant attention weights (o & 255 == t0 & 255 for all o).
    const float4 a = __ldg(&att[t0 & 255]);

    int o = t0;
    // Main body: ILP front-batched loads.
    while (o + (ILP - 1) * stride < TOTAL_O) {
        float2 d[ILP];
        #pragma unroll
        for (int k = 0; k < ILP; k++)
            d[k] = __ldcs(&data[o + k * stride]);

        #pragma unroll
        for (int k = 0; k < ILP; k++) {
            float y0 = tab_lookup_fast(d[k].x);
            float y1 = tab_lookup_fast(d[k].y);
            // One uniform (almost always not-taken) fixup per float2.
            float mx = fmaxf(fabsf(d[k].x), fabsf(d[k].y));
            if (__ballot_sync(0xffffffffu, mx >= 4.0f)) {
                if (fabsf(d[k].x) >= 4.0f)
                    y0 = f3_exact(d[k].x, c2l, b2l, angles, velocity);
                if (fabsf(d[k].y) >= 4.0f)
                    y1 = f3_exact(d[k].y, c2l, b2l, angles, velocity);
            }
            float4 ov;
            ov.x = a.x * y0;  ov.y = a.y * y0;
            ov.z = a.z * y1;  ov.w = a.w * y1;
            __stcs(&out[o + k * stride], ov);
        }
        o += ILP * stride;
    }
    // Tail.
    for (; o < TOTAL_O; o += stride) {
        float2 dv = __ldcs(&data[o]);
        float y0 = tab_lookup_fast(dv.x);
        float y1 = tab_lookup_fast(dv.y);
        float mx = fmaxf(fabsf(dv.x), fabsf(dv.y));
        if (__ballot_sync(0xffffffffu, mx >= 4.0f)) {
            if (fabsf(dv.x) >= 4.0f)
                y0 = f3_exact(dv.x, c2l, b2l, angles, velocity);
            if (fabsf(dv.y) >= 4.0f)
                y1 = f3_exact(dv.y, c2l, b2l, angles, velocity);
        }
        float4 ov;
        ov.x = a.x * y0;  ov.y = a.y * y0;
        ov.z = a.z * y1;  ov.w = a.w * y1;
        __stcs(&out[o], ov);
    }
}

extern "C" void kernel_launch(void* const* d_in, const int* in_sizes, int n_in,
                              void* d_out, int out_size)
{
    const float2* data     = (const float2*)d_in[0];  // [32768, 512] f32
    const float*  angles   = (const float*) d_in[1];  // [17]
    const float*  velocity = (const float*) d_in[2];  // [17]
    const float4* att      = (const float4*)d_in[3];  // [1024] f32
    const float*  coeff    = (const float*) d_in[4];  // [1]
    const float*  bias     = (const float*) d_in[5];  // [1]
    float4* out = (float4*)d_out;

    static bool attr_set = false;
    if (!attr_set) {
        cudaFuncSetAttribute(macunit_map_kernel,
                             cudaFuncAttributeMaxDynamicSharedMemorySize,
                             TAB_BYTES);
        attr_set = true;
    }

    build_table_kernel<<<(TAB_INTERVALS + 255) / 256, 256>>>(angles, velocity, coeff, bias);

    macunit_map_kernel<<<MAP_BLOCKS, MAP_THREADS, TAB_BYTES>>>(
        data, att, angles, velocity, coeff, bias, out);
}